// round 7
// baseline (speedup 1.0000x reference)
#include <cuda_runtime.h>
#include <math.h>
#include <float.h>

#define N 256
#define RPB 2
#define NBLK (N / RPB)        // 128 blocks, single wave
#define THREADS 512
#define FULL 0xffffffffu

__device__ float g_psum[NBLK];
__device__ float g_pcnt[NBLK];
__device__ unsigned int g_ticket = 0;   // reset by last block each launch

// Dynamic smem: full E, 8192 float4 = 128KB, swizzled: row j chunk c at j*32+((c+j)&31)
extern __shared__ float4 sE[];

__global__ void __launch_bounds__(THREADS, 1)
triplet_fused(const float* __restrict__ emb,
              const int*   __restrict__ lab32,
              float*       __restrict__ out) {
    __shared__ float4 sPart[N];          // upper-half partials (d0,d1,norm,-)
    __shared__ float  normL[N];          // lower-half norm partials
    __shared__ float  Dmat[RPB * N];
    __shared__ float  negd[RPB * N];
    __shared__ unsigned short pairs[RPB * N];
    __shared__ int    cnts[16], ofs[16];
    __shared__ int    np_sh;
    __shared__ float  wsum[16], wcnt[16];
    __shared__ int    sh_flag, sh_last;

    const int b = blockIdx.x;
    const int t = threadIdx.x;
    const int w = t >> 5, l = t & 31;

    // ---- Stage E into smem with cp.async (no RF round-trip, swizzled dst).
    const float4* E4 = reinterpret_cast<const float4*>(emb);
    unsigned sb = (unsigned)__cvta_generic_to_shared(sE);
#pragma unroll
    for (int p = 0; p < 16; ++p) {
        const int g = p * THREADS + t;
        const int j = g >> 5, c = g & 31;
        unsigned dst = sb + ((unsigned)((j << 5) + ((c + j) & 31)) << 4);
        asm volatile("cp.async.cg.shared.global [%0], [%1], 16;"
                     :: "r"(dst), "l"(E4 + g));
    }
    asm volatile("cp.async.commit_group;");

    // ---- Label dtype sniff while copies fly. int64 LE labels (0..15) have
    // all-zero odd 32-bit words; words [0..255] in-bounds for both layouts.
    if (w == 0) {
        unsigned any = 0;
#pragma unroll
        for (int k = 0; k < 4; ++k)
            any |= (unsigned)lab32[2 * (l + 32 * k) + 1];
        unsigned bal = __ballot_sync(FULL, any != 0);
        if (l == 0) sh_flag = (bal != 0);
    }
    asm volatile("cp.async.wait_group 0;");
    __syncthreads();   // S1: sE + sh_flag ready

    const bool is64 = (sh_flag == 0);
    const int  i0 = b * RPB, i1 = i0 + 1;
    const int  row = t & 255, half = t >> 8;

    // lower half prefetches labels early (latency hidden under FFMA loop)
    int labT = 0, labI0 = 0, labI1 = 0;
    if (half == 0) {
        labT  = is64 ? lab32[2 * t]  : lab32[t];
        labI0 = is64 ? lab32[2 * i0] : lab32[i0];
        labI1 = is64 ? lab32[2 * i1] : lab32[i1];
    }

    // ---- Phase 1: each half computes 16 chunks of dot0, dot1, |e_row|^2.
    const float4* rowp = sE + (row << 5);
    const float4* rA   = sE + (i0  << 5);
    const float4* rB   = sE + (i1  << 5);
    const int c0 = half << 4;
    float d0a = 0.f, d0b = 0.f, d1a = 0.f, d1b = 0.f, na = 0.f, nb = 0.f;
#pragma unroll
    for (int cc = 0; cc < 16; cc += 2) {
        const int c = c0 + cc;
        float4 bv = rowp[(c + row) & 31];       // conflict-free (swizzle)
        float4 a0 = rA[(c + i0) & 31];          // uniform -> broadcast
        float4 a1 = rB[(c + i1) & 31];
        d0a += bv.x*a0.x + bv.y*a0.y + bv.z*a0.z + bv.w*a0.w;
        d1a += bv.x*a1.x + bv.y*a1.y + bv.z*a1.z + bv.w*a1.w;
        na  += bv.x*bv.x + bv.y*bv.y + bv.z*bv.z + bv.w*bv.w;
        float4 bw = rowp[(c + 1 + row) & 31];
        float4 b0 = rA[(c + 1 + i0) & 31];
        float4 b1 = rB[(c + 1 + i1) & 31];
        d0b += bw.x*b0.x + bw.y*b0.y + bw.z*b0.z + bw.w*b0.w;
        d1b += bw.x*b1.x + bw.y*b1.y + bw.z*b1.z + bw.w*b1.w;
        nb  += bw.x*bw.x + bw.y*bw.y + bw.z*bw.z + bw.w*bw.w;
    }
    const float dp0 = d0a + d0b, dp1 = d1a + d1b, nn = na + nb;
    if (half) sPart[row] = make_float4(dp0, dp1, nn, 0.f);
    else      normL[row] = nn;
    __syncthreads();   // S2

    bool posr0 = false, posr1 = false;
    if (half == 0) {
        const float4 up = sPart[t];
        const float dot0 = dp0 + up.x, dot1 = dp1 + up.y;
        const float nt   = nn + up.z;
        const float nI0  = normL[i0] + sPart[i0].z;   // broadcast reads
        const float nI1  = normL[i1] + sPart[i1].z;
        const float D0 = sqrtf(fmaxf(nI0 + nt - 2.f * dot0, 1e-4f));
        const float D1 = sqrtf(fmaxf(nI1 + nt - 2.f * dot1, 1e-4f));
        posr0 = (labT == labI0) && (t != i0);
        posr1 = (labT == labI1) && (t != i1);
        Dmat[t]     = D0;
        Dmat[N + t] = D1;
        // negatives include t==i (reference's (1-pos) keeps diagonal; d_ii=0.01)
        negd[t]     = posr0 ? -FLT_MAX : D0;
        negd[N + t] = posr1 ? -FLT_MAX : D1;
        unsigned bal0 = __ballot_sync(FULL, posr0);
        unsigned bal1 = __ballot_sync(FULL, posr1);
        if (l == 0) { cnts[w] = __popc(bal0); cnts[8 + w] = __popc(bal1); }
    }
    __syncthreads();   // S3

    if (w == 0) {      // exclusive scan of 16 counts -> deterministic offsets
        int x = (l < 16) ? cnts[l] : 0;
        const int v = x;
#pragma unroll
        for (int d = 1; d < 32; d <<= 1) {
            int y = __shfl_up_sync(FULL, x, d);
            if (l >= d) x += y;
        }
        if (l < 16) ofs[l] = x - v;
        if (l == 15) np_sh = x;
    }
    __syncthreads();   // S4

    if (half == 0) {
        unsigned bal0 = __ballot_sync(FULL, posr0);
        unsigned bal1 = __ballot_sync(FULL, posr1);
        const unsigned lm = (1u << l) - 1u;
        if (posr0) pairs[ofs[w]     + __popc(bal0 & lm)] = (unsigned short)t;
        if (posr1) pairs[ofs[8 + w] + __popc(bal1 & lm)] = (unsigned short)(256 | t);
    }
    __syncthreads();   // S5

    // ---- Phase 3: one warp per positive pair (16 warps).
    float lsum = 0.f, lcnt = 0.f;
    const int npair = np_sh;
    for (int p = w; p < npair; p += 16) {
        const unsigned pr = pairs[p];
        const int r = pr >> 8, k = pr & 255;
        const float Dk = Dmat[r * N + k];
        const float* nd = negd + r * N;
        float mx = -FLT_MAX, mn = FLT_MAX;
#pragma unroll
        for (int u = 0; u < 8; ++u) {
            float v = nd[u * 32 + l];
            mx = fmaxf(mx, v);
            mn = fminf(mn, v > Dk ? v : FLT_MAX);
        }
#pragma unroll
        for (int s = 16; s > 0; s >>= 1) {
            mx = fmaxf(mx, __shfl_down_sync(FULL, mx, s));
            mn = fminf(mn, __shfl_down_sync(FULL, mn, s));
        }
        if (l == 0) {
            // semi-hard if strictly-farther negative exists, else easiest neg
            float semi = (mn < FLT_MAX) ? (Dk - mn) : (Dk - mx);
            lsum += fmaxf(semi + 1.0f, 0.f);   // relu(semi + MARGIN)
            lcnt += 1.f;
        }
    }
    if (l == 0) { wsum[w] = lsum; wcnt[w] = lcnt; }
    __syncthreads();   // S6

    if (t == 0) {
        float S = 0.f, C = 0.f;
#pragma unroll
        for (int k = 0; k < 16; ++k) { S += wsum[k]; C += wcnt[k]; }
        g_psum[b] = S;
        g_pcnt[b] = C;
        __threadfence();
        unsigned tk = atomicAdd(&g_ticket, 1u);
        sh_last = (tk == NBLK - 1);
        if (sh_last) g_ticket = 0;   // all blocks already added; replay-safe
    }
    __syncthreads();   // S7

    // ---- Last block: reduce 128 per-block partials (L1-bypass reads).
    if (sh_last && t < NBLK) {
        float ss = __ldcg(&g_psum[t]);
        float cc = __ldcg(&g_pcnt[t]);
#pragma unroll
        for (int s = 16; s > 0; s >>= 1) {
            ss += __shfl_down_sync(FULL, ss, s);
            cc += __shfl_down_sync(FULL, cc, s);
        }
        if (l == 0) { wsum[w] = ss; wcnt[w] = cc; }
    }
    __syncthreads();   // S8
    if (sh_last && t == 0) {
        float S = 0.f, C = 0.f;
#pragma unroll
        for (int k = 0; k < 4; ++k) { S += wsum[k]; C += wcnt[k]; }
        out[0] = S / C;
    }
}

extern "C" void kernel_launch(void* const* d_in, const int* in_sizes, int n_in,
                              void* d_out, int out_size) {
    const float* emb  = (const float*)d_in[0];
    const int*   labs = (const int*)d_in[1];
    float* out = (float*)d_out;
    cudaFuncSetAttribute(triplet_fused,
                         cudaFuncAttributeMaxDynamicSharedMemorySize, 131072);
    triplet_fused<<<NBLK, THREADS, 131072>>>(emb, labs, out);
}